// round 3
// baseline (speedup 1.0000x reference)
#include <cuda_runtime.h>
#include <cstdint>

#define B_  2
#define S_  2048
#define H_  16
#define D_  128
#define BR  128
#define BC  64
#define NTHREADS 256
#define KP  132                       // smem row pitch (floats)
#define TABOFF (2 * BC * KP)          // 16896 floats; Q staging (128*KP) aliases K+V exactly
#define SMEM_FLOATS (TABOFF + S_)
#define SMEM_BYTES  (SMEM_FLOATS * 4) // 75776
#define LOG2E 1.4426950408889634f

__device__ __forceinline__ uint32_t f2tf(float x) {
    uint32_t u; asm("cvt.rna.tf32.f32 %0, %1;" : "=r"(u) : "f"(x)); return u;
}

__device__ __forceinline__ void mma8(float* c, const uint32_t* a, uint32_t b0, uint32_t b1) {
    asm volatile(
        "mma.sync.aligned.m16n8k8.row.col.f32.tf32.tf32.f32 "
        "{%0,%1,%2,%3}, {%4,%5,%6,%7}, {%8,%9}, {%0,%1,%2,%3};"
        : "+f"(c[0]), "+f"(c[1]), "+f"(c[2]), "+f"(c[3])
        : "r"(a[0]), "r"(a[1]), "r"(a[2]), "r"(a[3]), "r"(b0), "r"(b1));
}

__global__ __launch_bounds__(NTHREADS, 1)
void fa_alibi_kernel(const float* __restrict__ qp, const float* __restrict__ kp,
                     const float* __restrict__ vp, float* __restrict__ op)
{
    extern __shared__ float sm[];
    float* ks  = sm;                // K tile [BC][KP]
    float* vs  = sm + BC * KP;      // V tile [BC][KP]
    float* tab = sm + TABOFF;       // bias table [S_]

    const int tid  = threadIdx.x;
    const int lane = tid & 31;
    const int warp = tid >> 5;
    const int qt   = 15 - (int)blockIdx.x;     // heavy tiles first
    const int bh   = blockIdx.y;
    const int b    = bh >> 4;
    const int h    = bh & 15;
    const int q0   = qt * BR;
    const int g    = lane >> 2;                // row group 0..7
    const int a4   = lane & 3;                 // quad lane 0..3

    // bias table in log2 domain: tab[d] = -slope * sqrt(d) * log2(e)
    const float slope = exp2f(-0.5f * (float)(h + 1));
    for (int i = tid; i < S_; i += NTHREADS)
        tab[i] = -slope * sqrtf((float)i) * LOG2E;

    // ---- stage Q tile (coalesced) into smem (aliases K/V region) ----
    {
        const float* qb = qp + ((size_t)(b * S_ + q0) * H_ + h) * D_;
        #pragma unroll
        for (int it = 0; it < 16; it++) {
            int j = tid + it * NTHREADS;
            int r = j >> 5, c4 = (j & 31) << 2;
            float4 t4 = *(const float4*)(qb + (size_t)r * (H_ * D_) + c4);
            *(float4*)(sm + r * KP + c4) = t4;
        }
    }
    __syncthreads();

    // ---- load Q fragments (tf32), 64 regs: rows 16*warp..+15 ----
    uint32_t qa[16][4];
    {
        const int r0 = 16 * warp + g;
        #pragma unroll
        for (int c = 0; c < 16; c++) {
            qa[c][0] = f2tf(sm[ r0      * KP + 8 * c     + a4]);
            qa[c][1] = f2tf(sm[(r0 + 8) * KP + 8 * c     + a4]);
            qa[c][2] = f2tf(sm[ r0      * KP + 8 * c + 4 + a4]);
            qa[c][3] = f2tf(sm[(r0 + 8) * KP + 8 * c + 4 + a4]);
        }
    }

    float o[16][4];
    #pragma unroll
    for (int n = 0; n < 16; n++) { o[n][0] = o[n][1] = o[n][2] = o[n][3] = 0.f; }
    float m0 = -1e30f, m1 = -1e30f, l0 = 0.f, l1 = 0.f;

    const int   row0 = q0 + 16 * warp + g;
    const int   row1 = row0 + 8;
    const float SC2  = 0.08838834764831845f * LOG2E;   // (1/sqrt(128)) * log2(e)

    const int    nkt      = 2 * (qt + 1);
    const size_t kvstride = (size_t)H_ * D_;
    const float* kbase = kp + ((size_t)(b * S_) * H_ + h) * D_;
    const float* vbase = vp + ((size_t)(b * S_) * H_ + h) * D_;

    for (int kt = 0; kt < nkt; kt++) {
        const int k0 = kt * BC;
        __syncthreads();   // protect smem K/V (and staged Q on first iter)

        // ---- load K,V tile, rounding to tf32 at store ----
        #pragma unroll
        for (int it = 0; it < 8; it++) {
            int j = tid + it * NTHREADS;
            int r = j >> 5, c4 = (j & 31) << 2;
            float4 t4 = *(const float4*)(kbase + (size_t)(k0 + r) * kvstride + c4);
            t4.x = __uint_as_float(f2tf(t4.x)); t4.y = __uint_as_float(f2tf(t4.y));
            t4.z = __uint_as_float(f2tf(t4.z)); t4.w = __uint_as_float(f2tf(t4.w));
            *(float4*)(ks + r * KP + c4) = t4;
            float4 u4 = *(const float4*)(vbase + (size_t)(k0 + r) * kvstride + c4);
            u4.x = __uint_as_float(f2tf(u4.x)); u4.y = __uint_as_float(f2tf(u4.y));
            u4.z = __uint_as_float(f2tf(u4.z)); u4.w = __uint_as_float(f2tf(u4.w));
            *(float4*)(vs + r * KP + c4) = u4;
        }
        __syncthreads();

        // ---- S = Q K^T  (8 n-tiles of 8 keys, 16 k-chunks of d) ----
        float sc[8][4];
        #pragma unroll
        for (int t = 0; t < 8; t++) { sc[t][0] = sc[t][1] = sc[t][2] = sc[t][3] = 0.f; }
        const uint32_t* ksu = (const uint32_t*)ks;
        #pragma unroll
        for (int c = 0; c < 16; c++) {
            #pragma unroll
            for (int t = 0; t < 8; t++) {
                uint32_t b0 = ksu[(8 * t + g) * KP + 8 * c     + a4];
                uint32_t b1 = ksu[(8 * t + g) * KP + 8 * c + 4 + a4];
                mma8(sc[t], qa[c], b0, b1);
            }
        }

        // ---- bias + causal mask + online softmax (log2 domain) ----
        const bool full = (k0 + BC) <= q0;
        float mt0 = -1e30f, mt1 = -1e30f;
        #pragma unroll
        for (int t = 0; t < 8; t++) {
            const int key0 = k0 + 8 * t + 2 * a4;
            const int key1 = key0 + 1;
            float s0, s1, s2, s3;
            if (full) {
                s0 = fmaf(sc[t][0], SC2, tab[row0 - key0]);
                s1 = fmaf(sc[t][1], SC2, tab[row0 - key1]);
                s2 = fmaf(sc[t][2], SC2, tab[row1 - key0]);
                s3 = fmaf(sc[t][3], SC2, tab[row1 - key1]);
            } else {
                int d00 = row0 - key0, d01 = row0 - key1, d10 = row1 - key0, d11 = row1 - key1;
                s0 = (d00 >= 0) ? fmaf(sc[t][0], SC2, tab[d00]) : -1e30f;
                s1 = (d01 >= 0) ? fmaf(sc[t][1], SC2, tab[d01]) : -1e30f;
                s2 = (d10 >= 0) ? fmaf(sc[t][2], SC2, tab[d10]) : -1e30f;
                s3 = (d11 >= 0) ? fmaf(sc[t][3], SC2, tab[d11]) : -1e30f;
            }
            sc[t][0] = s0; sc[t][1] = s1; sc[t][2] = s2; sc[t][3] = s3;
            mt0 = fmaxf(mt0, fmaxf(s0, s1));
            mt1 = fmaxf(mt1, fmaxf(s2, s3));
        }
        mt0 = fmaxf(mt0, __shfl_xor_sync(0xffffffffu, mt0, 1));
        mt0 = fmaxf(mt0, __shfl_xor_sync(0xffffffffu, mt0, 2));
        mt1 = fmaxf(mt1, __shfl_xor_sync(0xffffffffu, mt1, 1));
        mt1 = fmaxf(mt1, __shfl_xor_sync(0xffffffffu, mt1, 2));

        const float mn0 = fmaxf(m0, mt0), mn1 = fmaxf(m1, mt1);
        const float es0 = exp2f(m0 - mn0), es1 = exp2f(m1 - mn1);
        m0 = mn0; m1 = mn1;

        float ls0 = 0.f, ls1 = 0.f;
        #pragma unroll
        for (int t = 0; t < 8; t++) {
            float p0 = exp2f(sc[t][0] - m0);
            float p1 = exp2f(sc[t][1] - m0);
            float p2 = exp2f(sc[t][2] - m1);
            float p3 = exp2f(sc[t][3] - m1);
            sc[t][0] = p0; sc[t][1] = p1; sc[t][2] = p2; sc[t][3] = p3;
            ls0 += p0 + p1; ls1 += p2 + p3;
        }
        ls0 += __shfl_xor_sync(0xffffffffu, ls0, 1);
        ls0 += __shfl_xor_sync(0xffffffffu, ls0, 2);
        ls1 += __shfl_xor_sync(0xffffffffu, ls1, 1);
        ls1 += __shfl_xor_sync(0xffffffffu, ls1, 2);
        l0 = l0 * es0 + ls0;
        l1 = l1 * es1 + ls1;
        #pragma unroll
        for (int n = 0; n < 16; n++) {
            o[n][0] *= es0; o[n][1] *= es0; o[n][2] *= es1; o[n][3] *= es1;
        }

        // ---- O += P V : C-frag -> A-frag via intra-quad shuffles ----
        const uint32_t* vsu = (const uint32_t*)vs;
        const int qb2  = lane & ~3;
        const int srcA = qb2 + (a4 >> 1);
        const int srcB = srcA + 2;
        const bool odd = (a4 & 1);
        #pragma unroll
        for (int t = 0; t < 8; t++) {
            float w00 = __shfl_sync(0xffffffffu, sc[t][0], srcA);
            float w01 = __shfl_sync(0xffffffffu, sc[t][1], srcA);
            float w02 = __shfl_sync(0xffffffffu, sc[t][0], srcB);
            float w03 = __shfl_sync(0xffffffffu, sc[t][1], srcB);
            float w10 = __shfl_sync(0xffffffffu, sc[t][2], srcA);
            float w11 = __shfl_sync(0xffffffffu, sc[t][3], srcA);
            float w12 = __shfl_sync(0xffffffffu, sc[t][2], srcB);
            float w13 = __shfl_sync(0xffffffffu, sc[t][3], srcB);
            uint32_t aP[4];
            aP[0] = f2tf(odd ? w01 : w00);
            aP[1] = f2tf(odd ? w11 : w10);
            aP[2] = f2tf(odd ? w03 : w02);
            aP[3] = f2tf(odd ? w13 : w12);
            #pragma unroll
            for (int n = 0; n < 16; n++) {
                uint32_t b0 = vsu[(8 * t +     a4) * KP + 8 * n + g];
                uint32_t b1 = vsu[(8 * t + 4 + a4) * KP + 8 * n + g];
                mma8(o[n], aP, b0, b1);
            }
        }
    }

    // ---- epilogue: O / l -> gmem ----
    const float inv0 = 1.0f / l0;
    const float inv1 = 1.0f / l1;
    float* ob0 = op + ((size_t)(b * S_ + row0) * H_ + h) * D_;
    float* ob1 = op + ((size_t)(b * S_ + row1) * H_ + h) * D_;
    #pragma unroll
    for (int n = 0; n < 16; n++) {
        int col = 8 * n + 2 * a4;
        float2 r0v = make_float2(o[n][0] * inv0, o[n][1] * inv0);
        float2 r1v = make_float2(o[n][2] * inv1, o[n][3] * inv1);
        *(float2*)(ob0 + col) = r0v;
        *(float2*)(ob1 + col) = r1v;
    }
}

extern "C" void kernel_launch(void* const* d_in, const int* in_sizes, int n_in,
                              void* d_out, int out_size)
{
    const float* q = (const float*)d_in[0];
    const float* k = (const float*)d_in[1];
    const float* v = (const float*)d_in[2];
    float* out = (float*)d_out;

    cudaFuncSetAttribute(fa_alibi_kernel,
                         cudaFuncAttributeMaxDynamicSharedMemorySize, SMEM_BYTES);
    dim3 grid(S_ / BR, B_ * H_);
    fa_alibi_kernel<<<grid, NTHREADS, SMEM_BYTES>>>(q, k, v, out);
}